// round 15
// baseline (speedup 1.0000x reference)
#include <cuda_runtime.h>
#include <cstdint>

// ---------------------------------------------------------------------------
// Problem constants
// ---------------------------------------------------------------------------
#define B 64
#define N 2048
#define DIM 768
#define POOL 1024
#define LEN 16
#define NOUT 2080                 // 2*LEN + N
#define C4 (DIM / 4)              // 192 float4 per row
#define NCHUNK 32
#define TOKPC (N / NCHUNK)        // 64
#define SCALAR_OFF ((size_t)B * NOUT * DIM)
#define KSTRIPE (DIM / 8)         // 96 k's per warp in sim
#define ROWS 4                    // pool rows per sim block

// ---------------------------------------------------------------------------
// Device scratch (no allocations). Only touched from device code — passing
// these symbols from host binds the host shadow copy (ATS trap).
// ---------------------------------------------------------------------------
__device__ __align__(16) float4 g_part[B * NCHUNK * C4];  // per-(b,chunk) sums
__device__ __align__(16) float  g_xnormT[DIM * B];        // x_norm^T [c][b]
__device__ unsigned long long   g_pack1[B];  // (flip(best)<<32)|~idx, stage 0
__device__ unsigned long long   g_pack2[B];  // stage 1

// ---------------------------------------------------------------------------
// order-monotonic float<->u32 mapping + pack/unpack. max(pack) == max value;
// ties -> lowest pool index (low word = ~idx). flip(v) > 0 for all finite v,
// so the re-armed 0 cells are always overwritten before any unpack.
// ---------------------------------------------------------------------------
__device__ __forceinline__ unsigned flip_f(float v) {
    unsigned b = __float_as_uint(v);
    return b ^ ((b & 0x80000000u) ? 0xffffffffu : 0x80000000u);
}
__device__ __forceinline__ float unflip_f(unsigned k) {
    return __uint_as_float(k ^ ((k & 0x80000000u) ? 0x80000000u : 0xffffffffu));
}
__device__ __forceinline__ unsigned long long pack_vi(float v, int idx) {
    return ((unsigned long long)flip_f(v) << 32) |
           (unsigned long long)(0xffffffffu - (unsigned)idx);
}
__device__ __forceinline__ int unpack_idx(unsigned long long p) {
    return (int)(0xffffffffu - (unsigned)(p & 0xffffffffu));
}
__device__ __forceinline__ float unpack_val(unsigned long long p) {
    return unflip_f((unsigned)(p >> 32));
}

// ---------------------------------------------------------------------------
// 1) Fused: copy x_embed -> out rows [32,2080) AND per-(b,chunk,c) sums.
//    grid = B*32 = 2048, block = 192. (Byte-identical to R9/R12 best.)
// ---------------------------------------------------------------------------
__global__ __launch_bounds__(C4) void copy_mean_kernel(
    const float4* __restrict__ x, float4* __restrict__ out4)
{
    int b     = blockIdx.x >> 5;
    int chunk = blockIdx.x & 31;
    int c4    = threadIdx.x;                         // 0..191

    size_t xbase = ((size_t)b * N + (size_t)chunk * TOKPC) * C4 + c4;
    size_t obase = ((size_t)b * NOUT + 2 * LEN + (size_t)chunk * TOKPC) * C4 + c4;

    float ax = 0.f, ay = 0.f, az = 0.f, aw = 0.f;
#pragma unroll 8
    for (int t = 0; t < TOKPC; ++t) {
        float4 v = x[xbase + (size_t)t * C4];
        out4[obase + (size_t)t * C4] = v;
        ax += v.x; ay += v.y; az += v.z; aw += v.w;
    }
    g_part[(b * NCHUNK + chunk) * C4 + c4] = make_float4(ax, ay, az, aw);
}

// ---------------------------------------------------------------------------
// 2) x_norm = l2norm(mean) -> g_xnormT (transposed); re-arms the per-batch
//    atomic-max cells for this replay.  grid=B, block=256. PDL.
// ---------------------------------------------------------------------------
__global__ __launch_bounds__(256) void xnorm_kernel()
{
    cudaGridDependencySynchronize();
    __shared__ float sh[8];
    int tid = threadIdx.x;
    int warp = tid >> 5, lane = tid & 31;
    int b = blockIdx.x;
    if (tid == 0) { g_pack1[b] = 0ull; g_pack2[b] = 0ull; }
    int c4 = tid;
    float sx = 0.f, sy = 0.f, sz = 0.f, sw = 0.f;
    if (c4 < C4) {
#pragma unroll
        for (int k = 0; k < NCHUNK; ++k) {
            float4 p = g_part[(b * NCHUNK + k) * C4 + c4];
            sx += p.x; sy += p.y; sz += p.z; sw += p.w;
        }
        const float invN = 1.0f / (float)N;
        sx *= invN; sy *= invN; sz *= invN; sw *= invN;
    }
    float ss = sx * sx + sy * sy + sz * sz + sw * sw;
#pragma unroll
    for (int o = 16; o > 0; o >>= 1) ss += __shfl_down_sync(0xffffffffu, ss, o);
    if (lane == 0) sh[warp] = ss;
    __syncthreads();
    if (tid == 0) {
        float tot = 0.f;
#pragma unroll
        for (int w = 0; w < 8; ++w) tot += sh[w];
        sh[0] = rsqrtf(fmaxf(tot, 1e-12f));
    }
    __syncthreads();
    if (c4 < C4) {
        float inv = sh[0];
        int c = c4 * 4;
        g_xnormT[(c + 0) * B + b] = sx * inv;
        g_xnormT[(c + 1) * B + b] = sy * inv;
        g_xnormT[(c + 2) * B + b] = sz * inv;
        g_xnormT[(c + 3) * B + b] = sw * inv;
    }
}

// ---------------------------------------------------------------------------
// 3) sim + INLINE argmax. Block = ROWS(4) pool rows; 8 warps split k; lane
//    owns batch pair (2*lane, 2*lane+1). Key norms computed inline. Warp 0
//    folds the 4 rows per batch and fires ONE packed RED.MAX per cell.
//    STAGE 1 computes the residual vector ON THE FLY:
//      x[b][k] = pk[idx1[b]][k] - xnormT[k][b]
//    (pk rows are lane-sequential -> L1-line friendly; 64 rows, L2-hot).
//    PDL: key rows staged to smem BEFORE the dependency sync.
//    grid = POOL/ROWS = 256, block = 256.
// ---------------------------------------------------------------------------
template <int STAGE>
__global__ __launch_bounds__(256) void sim_kernel(
    const float* __restrict__ keys, const float* __restrict__ pk)
{
    __shared__ float  skey[ROWS][DIM];                 // 12 KB
    __shared__ float4 spartA[8][32];                   // rows 0,1 partials
    __shared__ float4 spartB[8][32];                   // rows 2,3 partials
    __shared__ float4 snorm[8];                        // 4 norms per warp
    __shared__ int    sidx[B];                         // STAGE 1: idx1

    int p0   = blockIdx.x * ROWS;
    int tid  = threadIdx.x;
    int warp = tid >> 5, lane = tid & 31;

    // ---- independent prefetch: key rows (keys are kernel inputs) ----
    {
        const float4* kr = (const float4*)(keys + (size_t)p0 * DIM);
#pragma unroll
        for (int i = tid; i < ROWS * C4; i += 256)
            ((float4*)skey)[i] = __ldg(kr + i);
    }
    cudaGridDependencySynchronize();                   // deps now valid
    if (STAGE && tid < B) sidx[tid] = unpack_idx(g_pack1[tid]);
    __syncthreads();

    int b0 = lane * 2;
    const float2* xv = (const float2*)g_xnormT + lane; // +k*(B/2)
    const float* pr0 = nullptr, * pr1 = nullptr;
    if (STAGE) {
        pr0 = pk + (size_t)sidx[b0] * DIM;
        pr1 = pk + (size_t)sidx[b0 + 1] * DIM;
    }

    float a00 = 0.f, a01 = 0.f, a10 = 0.f, a11 = 0.f;  // rows 0,1 x batches
    float a20 = 0.f, a21 = 0.f, a30 = 0.f, a31 = 0.f;  // rows 2,3 x batches
    float ss0 = 0.f, ss1 = 0.f, ss2 = 0.f, ss3 = 0.f;  // norms (lane-uniform)
    int kb = warp * KSTRIPE;
#pragma unroll 8
    for (int i = 0; i < KSTRIPE; ++i) {
        int k = kb + i;
        float2 xn = xv[(size_t)k * (B / 2)];
        float x0, x1;
        if (STAGE) {
            x0 = pr0[k] - xn.x;
            x1 = pr1[k] - xn.y;
        } else {
            x0 = xn.x;
            x1 = xn.y;
        }
        float kv0 = skey[0][k], kv1 = skey[1][k];
        float kv2 = skey[2][k], kv3 = skey[3][k];
        ss0 += kv0 * kv0; ss1 += kv1 * kv1;
        ss2 += kv2 * kv2; ss3 += kv3 * kv3;
        a00 += kv0 * x0; a01 += kv0 * x1;
        a10 += kv1 * x0; a11 += kv1 * x1;
        a20 += kv2 * x0; a21 += kv2 * x1;
        a30 += kv3 * x0; a31 += kv3 * x1;
    }
    spartA[warp][lane] = make_float4(a00, a01, a10, a11);
    spartB[warp][lane] = make_float4(a20, a21, a30, a31);
    if (lane == 0) snorm[warp] = make_float4(ss0, ss1, ss2, ss3);
    __syncthreads();
    if (warp == 0) {
        float t00 = 0.f, t01 = 0.f, t10 = 0.f, t11 = 0.f;
        float t20 = 0.f, t21 = 0.f, t30 = 0.f, t31 = 0.f;
        float n0 = 0.f, n1 = 0.f, n2 = 0.f, n3 = 0.f;
#pragma unroll
        for (int w = 0; w < 8; ++w) {
            float4 va = spartA[w][lane];
            float4 vb = spartB[w][lane];
            t00 += va.x; t01 += va.y; t10 += va.z; t11 += va.w;
            t20 += vb.x; t21 += vb.y; t30 += vb.z; t31 += vb.w;
            float4 nn = snorm[w];
            n0 += nn.x; n1 += nn.y; n2 += nn.z; n3 += nn.w;
        }
        float i0 = rsqrtf(fmaxf(n0, 1e-12f));
        float i1 = rsqrtf(fmaxf(n1, 1e-12f));
        float i2 = rsqrtf(fmaxf(n2, 1e-12f));
        float i3 = rsqrtf(fmaxf(n3, 1e-12f));
        // fold 4 rows per batch, ascending p with strict > (lowest p on ties)
        float v0 = t00 * i0; int q0 = p0;
        float c1 = t10 * i1; if (c1 > v0) { v0 = c1; q0 = p0 + 1; }
        float c2 = t20 * i2; if (c2 > v0) { v0 = c2; q0 = p0 + 2; }
        float c3 = t30 * i3; if (c3 > v0) { v0 = c3; q0 = p0 + 3; }
        float v1 = t01 * i0; int q1 = p0;
        float d1 = t11 * i1; if (d1 > v1) { v1 = d1; q1 = p0 + 1; }
        float d2 = t21 * i2; if (d2 > v1) { v1 = d2; q1 = p0 + 2; }
        float d3 = t31 * i3; if (d3 > v1) { v1 = d3; q1 = p0 + 3; }
        unsigned long long* packs = STAGE ? g_pack2 : g_pack1;
        atomicMax(&packs[b0],     pack_vi(v0, q0));
        atomicMax(&packs[b0 + 1], pack_vi(v1, q1));
    }
}

// ---------------------------------------------------------------------------
// 4) finish: both gathers spread over 256 blocks + scalar in block 256. PDL.
//    which=0 -> residual_prompt[idx2] @ out rows [0,16)
//    which=1 -> prompt[idx1]          @ out rows [16,32)
// ---------------------------------------------------------------------------
__global__ __launch_bounds__(256) void finish_kernel(
    const float4* __restrict__ prompt4,
    const float4* __restrict__ rprompt4,
    float4* __restrict__ out4,
    float* __restrict__ out_scalar,
    int write_scalar)
{
    cudaGridDependencySynchronize();
    if (blockIdx.x == 4 * B) {
        __shared__ float sh[2];
        if (write_scalar && threadIdx.x < 64) {
            float v = unpack_val(g_pack1[threadIdx.x]) +
                      unpack_val(g_pack2[threadIdx.x]);
#pragma unroll
            for (int o = 16; o > 0; o >>= 1)
                v += __shfl_down_sync(0xffffffffu, v, o);
            if ((threadIdx.x & 31) == 0) sh[threadIdx.x >> 5] = v;
        }
        __syncthreads();
        if (write_scalar && threadIdx.x == 0)
            out_scalar[SCALAR_OFF] = (sh[0] + sh[1]) * (1.0f / (float)B);
        return;
    }
    int b     = blockIdx.x >> 2;
    int which = (blockIdx.x >> 1) & 1;
    int half  = blockIdx.x & 1;
    int idx = which ? unpack_idx(g_pack1[b]) : unpack_idx(g_pack2[b]);
    const int HQ = (LEN / 2) * C4;                   // 1536 float4 per half
    const float4* src = (which ? prompt4 : rprompt4)
                        + (size_t)idx * LEN * C4 + (size_t)half * HQ;
    float4* dst = out4 + ((size_t)b * NOUT + (which ? LEN : 0)
                          + (size_t)half * (LEN / 2)) * C4;
#pragma unroll
    for (int i = 0; i < HQ / 256; ++i)
        dst[threadIdx.x + i * 256] = src[threadIdx.x + i * 256];
}

// ---------------------------------------------------------------------------
// PDL launch helper
// ---------------------------------------------------------------------------
template <typename K, typename... Args>
static void launch_pdl(dim3 grid, dim3 block, K kernel, Args... args)
{
    cudaLaunchConfig_t cfg = {};
    cfg.gridDim = grid;
    cfg.blockDim = block;
    cfg.dynamicSmemBytes = 0;
    cfg.stream = 0;                      // legacy default (capture) stream
    cudaLaunchAttribute attr[1];
    attr[0].id = cudaLaunchAttributeProgrammaticStreamSerialization;
    attr[0].val.programmaticStreamSerializationAllowed = 1;
    cfg.attrs = attr;
    cfg.numAttrs = 1;
    cudaLaunchKernelEx(&cfg, kernel, args...);
}

// ---------------------------------------------------------------------------
// launch
// ---------------------------------------------------------------------------
extern "C" void kernel_launch(void* const* d_in, const int* in_sizes, int n_in,
                              void* d_out, int out_size)
{
    // Map inputs by element count (order-robust).
    const float* x_embed = nullptr;
    const float* prompt = nullptr, * rprompt = nullptr;
    const float* pkey = nullptr, * rpkey = nullptr;
    for (int i = 0; i < n_in; ++i) {
        int sz = in_sizes[i];
        if (sz == B * N * DIM) x_embed = (const float*)d_in[i];
        else if (sz == POOL * LEN * DIM) {
            if (!prompt) prompt = (const float*)d_in[i];
            else if (!rprompt) rprompt = (const float*)d_in[i];
        } else if (sz == POOL * DIM) {
            if (!pkey) pkey = (const float*)d_in[i];
            else if (!rpkey) rpkey = (const float*)d_in[i];
        }
    }
    float* out = (float*)d_out;

    copy_mean_kernel<<<B * NCHUNK, C4>>>((const float4*)x_embed, (float4*)out);
    launch_pdl(dim3(B), dim3(256), xnorm_kernel);
    launch_pdl(dim3(POOL / ROWS), dim3(256), sim_kernel<0>, pkey, pkey);
    launch_pdl(dim3(POOL / ROWS), dim3(256), sim_kernel<1>, rpkey, pkey);
    int write_scalar = ((size_t)out_size > SCALAR_OFF) ? 1 : 0;
    launch_pdl(dim3(4 * B + 1), dim3(256), finish_kernel,
               (const float4*)prompt, (const float4*)rprompt, (float4*)out,
               out, write_scalar);
}